// round 12
// baseline (speedup 1.0000x reference)
#include <cuda_runtime.h>
#include <cuda_fp16.h>
#include <mma.h>
#include <cstdint>

using namespace nvcuda;

#define NN 50000
#define EE 800000
#define IND 16
#define HD 128
#define WW 256          // fused width (policy 0..127, value 128..255)
#define SCB 49          // scan blocks (49 * 1024 >= 50000)
#define ZLD 264         // z/A tile leading dim (elements)

// ---------------- device scratch (static, no allocation; zero-initialized) ----
__device__ int    g_cnt[NN + 16];
__device__ int    g_off[NN + 1];
__device__ int    g_pub[64];                   // chained-scan publish slots
__device__ int    g_slot[EE];                  // per-edge intra-row slot
__device__ int2   g_edge[EE + NN];             // (src, norm-bits) per CSR slot
__device__ float  g_dis[NN];
__device__ __half g_w2h[WW * HD];              // fp16 fused [Wc2;Wv2]
__device__ __half g_h[(size_t)NN * WW];        // relu(layer1), fp16
__device__ __half g_aggh[(size_t)(NN + 32) * WW]; // A_norm @ h, fp16 (+pad rows)

// ---------------- graph prep ----------------
// g_cnt/g_pub zero on entry (zero-init statics; re-zeroed by k_layer1 each call)
__global__ void k_count(const int* __restrict__ ei,
                        const float* __restrict__ Wc2,
                        const float* __restrict__ Wv2) {
    int e = blockIdx.x * blockDim.x + threadIdx.x;
    if (e < EE) {
        int d = ei[EE + e];
        g_slot[e] = atomicAdd(&g_cnt[d], 1);   // slot within row d
    }
    // piggyback: fp16 weight conversion for the tensor-core gemm2
    if (e < WW * HD)
        g_w2h[e] = __float2half((e < HD * HD) ? Wc2[e] : Wv2[e - HD * HD]);
}

// fused single-pass scan: each block scans its 1024-elem range, chains the
// prefix through g_pub (publish prefix+total+1; 0 = unpublished).
__global__ void k_scan() {
    __shared__ int ss[256];
    __shared__ int spfx;
    int b = blockIdx.x, t = threadIdx.x;
    int i0 = (b * 256 + t) * 4;
    int4 c = {0, 0, 0, 0};
    int s = 0;
    if (i0 < NN) {
        c = *(const int4*)&g_cnt[i0];
        c.x += 1; c.y += 1; c.z += 1; c.w += 1;
        s = c.x + c.y + c.z + c.w;
    }
    ss[t] = s;
    __syncthreads();
#pragma unroll
    for (int off = 1; off < 256; off <<= 1) {
        int u = (t >= off) ? ss[t - off] : 0;
        __syncthreads();
        ss[t] += u;
        __syncthreads();
    }
    int total = ss[255];
    if (t == 0) {
        int p = 0;
        if (b > 0) {
            while ((p = *(volatile int*)&g_pub[b - 1]) == 0) {}
            p -= 1;
        }
        atomicExch(&g_pub[b], p + total + 1);   // publish inclusive prefix (+1)
        spfx = p;
        if (b == SCB - 1) g_off[NN] = p + total;
    }
    __syncthreads();
    int run = ss[t] - s + spfx;
    if (i0 < NN) {
        g_off[i0]     = run; g_dis[i0]     = rsqrtf((float)c.x); run += c.x;
        g_off[i0 + 1] = run; g_dis[i0 + 1] = rsqrtf((float)c.y); run += c.y;
        g_off[i0 + 2] = run; g_dis[i0 + 2] = rsqrtf((float)c.z); run += c.z;
        g_off[i0 + 3] = run; g_dis[i0 + 3] = rsqrtf((float)c.w);
    }
}

// fill CSR with packed (src, norm): position from precomputed slot, NO atomics
__global__ void k_fill(const int* __restrict__ ei) {
    int i = blockIdx.x * blockDim.x + threadIdx.x;
    if (i < EE) {
        int s = ei[i];
        int d = ei[EE + i];
        float nw = g_dis[s] * g_dis[d];
        g_edge[g_off[d] + g_slot[i]] = make_int2(s, __float_as_int(nw));
    } else if (i < EE + NN) {
        int n = i - EE;
        float ds = g_dis[n];
        g_edge[g_off[n + 1] - 1] = make_int2(n, __float_as_int(ds * ds));
    }
}

// ------- fused layer 1: 16 nodes/block -------
// gather phase: 4 lanes/edge (float4 of x), 8 edges in flight per warp
// dense phase: thread t = fused output col; W1 amortized over 16 nodes
// also: re-zero g_cnt/g_pub for the next call
__global__ void __launch_bounds__(256) k_layer1(const float* __restrict__ x,
                                                const float* __restrict__ Wc1,
                                                const float* __restrict__ Wv1,
                                                const float* __restrict__ bc1,
                                                const float* __restrict__ bv1) {
    __shared__ float xs[16][IND];
    int t = threadIdx.x, w = t >> 5, lane = t & 31;
    int node0 = blockIdx.x * 16;

    // counter/flag cleanup for next call
    int gid = blockIdx.x * 256 + t;
    if (gid < NN + 16) g_cnt[gid] = 0;
    if (blockIdx.x == 0 && t < 64) g_pub[t] = 0;

    int slot = lane >> 2, part = lane & 3;     // 8 edge slots x 4 row parts
#pragma unroll
    for (int q = 0; q < 2; q++) {
        int node = node0 + w * 2 + q;
        if (node < NN) {
            int jb = g_off[node], je = g_off[node + 1];
            float4 acc = {0.f, 0.f, 0.f, 0.f};
            for (int j = jb + slot; j < je; j += 8) {
                int2 e = g_edge[j];
                float nw = __int_as_float(e.y);
                float4 xv = __ldg((const float4*)(x + e.x * IND) + part);
                acc.x = fmaf(nw, xv.x, acc.x);
                acc.y = fmaf(nw, xv.y, acc.y);
                acc.z = fmaf(nw, xv.z, acc.z);
                acc.w = fmaf(nw, xv.w, acc.w);
            }
            // reduce across the 8 slots (stride-4 lanes)
#pragma unroll
            for (int off = 16; off >= 4; off >>= 1) {
                acc.x += __shfl_down_sync(0xffffffffu, acc.x, off);
                acc.y += __shfl_down_sync(0xffffffffu, acc.y, off);
                acc.z += __shfl_down_sync(0xffffffffu, acc.z, off);
                acc.w += __shfl_down_sync(0xffffffffu, acc.w, off);
            }
            if (lane < 4) *(float4*)&xs[w * 2 + q][lane * 4] = acc;
        }
    }
    __syncthreads();

    const float4* wr = (const float4*)((t < HD) ? (Wc1 + t * IND)
                                                : (Wv1 + (t - HD) * IND));
    float4 w0 = __ldg(&wr[0]), w1 = __ldg(&wr[1]);
    float4 w2 = __ldg(&wr[2]), w3 = __ldg(&wr[3]);
    float bias = (t < HD) ? __ldg(&bc1[t]) : __ldg(&bv1[t - HD]);
#pragma unroll
    for (int n = 0; n < 16; n++) {
        int node = node0 + n;
        if (node >= NN) break;
        float a = bias;
        a = fmaf(w0.x, xs[n][0],  a); a = fmaf(w0.y, xs[n][1],  a);
        a = fmaf(w0.z, xs[n][2],  a); a = fmaf(w0.w, xs[n][3],  a);
        a = fmaf(w1.x, xs[n][4],  a); a = fmaf(w1.y, xs[n][5],  a);
        a = fmaf(w1.z, xs[n][6],  a); a = fmaf(w1.w, xs[n][7],  a);
        a = fmaf(w2.x, xs[n][8],  a); a = fmaf(w2.y, xs[n][9],  a);
        a = fmaf(w2.z, xs[n][10], a); a = fmaf(w2.w, xs[n][11], a);
        a = fmaf(w3.x, xs[n][12], a); a = fmaf(w3.y, xs[n][13], a);
        a = fmaf(w3.z, xs[n][14], a); a = fmaf(w3.w, xs[n][15], a);
        g_h[(size_t)node * WW + t] = __float2half(fmaxf(a, 0.f));
    }
}

// ---------------- SpMM on h (256-wide, fp16 gather): aggh = A_norm @ h ------
__device__ __forceinline__ void acc8(float* acc, float nw, uint4 v) {
    float2 p;
    p = __half22float2(*(const __half2*)&v.x);
    acc[0] = fmaf(nw, p.x, acc[0]); acc[1] = fmaf(nw, p.y, acc[1]);
    p = __half22float2(*(((const __half2*)&v.x) + 1));
    acc[2] = fmaf(nw, p.x, acc[2]); acc[3] = fmaf(nw, p.y, acc[3]);
    p = __half22float2(*(const __half2*)&v.z);
    acc[4] = fmaf(nw, p.x, acc[4]); acc[5] = fmaf(nw, p.y, acc[5]);
    p = __half22float2(*(((const __half2*)&v.z) + 1));
    acc[6] = fmaf(nw, p.x, acc[6]); acc[7] = fmaf(nw, p.y, acc[7]);
}

__global__ void __launch_bounds__(256) k_spmmh() {
    int w = threadIdx.x >> 5, lane = threadIdx.x & 31;
    int node = blockIdx.x * 8 + w;
    if (node >= NN) return;
    int jb = g_off[node], je = g_off[node + 1];
    const __half* hp = g_h + (size_t)lane * 8;
    float acc[8];
#pragma unroll
    for (int i = 0; i < 8; i++) acc[i] = 0.f;
    int j = jb;
    for (; j + 4 <= je; j += 4) {
        int2 e0 = g_edge[j],     e1 = g_edge[j + 1];
        int2 e2 = g_edge[j + 2], e3 = g_edge[j + 3];
        uint4 v0 = __ldg((const uint4*)(hp + (size_t)e0.x * WW));
        uint4 v1 = __ldg((const uint4*)(hp + (size_t)e1.x * WW));
        uint4 v2 = __ldg((const uint4*)(hp + (size_t)e2.x * WW));
        uint4 v3 = __ldg((const uint4*)(hp + (size_t)e3.x * WW));
        acc8(acc, __int_as_float(e0.y), v0);
        acc8(acc, __int_as_float(e1.y), v1);
        acc8(acc, __int_as_float(e2.y), v2);
        acc8(acc, __int_as_float(e3.y), v3);
    }
    for (; j < je; j++) {
        int2 e = g_edge[j];
        uint4 v = __ldg((const uint4*)(hp + (size_t)e.x * WW));
        acc8(acc, __int_as_float(e.y), v);
    }
    __half2 ho[4];
#pragma unroll
    for (int i = 0; i < 4; i++)
        ho[i] = __floats2half2_rn(acc[i * 2], acc[i * 2 + 1]);
    *(uint4*)(g_aggh + (size_t)node * WW + lane * 8) = *(uint4*)ho;
}

// ---------------- dense layer 2 + heads (tensor cores) ----------------
__global__ void __launch_bounds__(256)
k_gemm2t(const float* __restrict__ bc2, const float* __restrict__ bv2,
         const float* __restrict__ Wp,  const float* __restrict__ Wvh,
         const float* __restrict__ bp,  const float* __restrict__ bvh,
         float* __restrict__ out) {
    __shared__ __align__(16) char sbuf[32 * ZLD * 4];   // 33.8 KB
    __half* As = (__half*)sbuf;                         // [32][ZLD] halves
    float*  zs = (float*)sbuf;                          // [32][ZLD] floats
    int t = threadIdx.x, warp = t >> 5;
    int node0 = blockIdx.x * 32;

    {
        const uint4* src = (const uint4*)(g_aggh + (size_t)node0 * WW);
        uint4* dst = (uint4*)As;
#pragma unroll
        for (int i = 0; i < 4; i++) {
            int idx = t + i * 256;
            int m = idx >> 5, c8 = idx & 31;
            dst[m * (ZLD / 8) + c8] = src[m * (WW / 8) + c8];
        }
    }
    __syncthreads();

    int nb = warp * 32;
    int kb = (warp < 4) ? 0 : HD;
    const __half* Bbase = g_w2h + nb * HD;

    wmma::fragment<wmma::accumulator, 16, 16, 16, float> c[2][2];
#pragma unroll
    for (int mi = 0; mi < 2; mi++)
#pragma unroll
        for (int ni = 0; ni < 2; ni++) wmma::fill_fragment(c[mi][ni], 0.f);

#pragma unroll
    for (int k = 0; k < HD; k += 16) {
        wmma::fragment<wmma::matrix_a, 16, 16, 16, __half, wmma::row_major> a0, a1;
        wmma::load_matrix_sync(a0, As + kb + k, ZLD);
        wmma::load_matrix_sync(a1, As + 16 * ZLD + kb + k, ZLD);
        wmma::fragment<wmma::matrix_b, 16, 16, 16, __half, wmma::col_major> b0, b1;
        wmma::load_matrix_sync(b0, Bbase + k, HD);
        wmma::load_matrix_sync(b1, Bbase + 16 * HD + k, HD);
        wmma::mma_sync(c[0][0], a0, b0, c[0][0]);
        wmma::mma_sync(c[0][1], a0, b1, c[0][1]);
        wmma::mma_sync(c[1][0], a1, b0, c[1][0]);
        wmma::mma_sync(c[1][1], a1, b1, c[1][1]);
    }
    __syncthreads();

#pragma unroll
    for (int mi = 0; mi < 2; mi++)
#pragma unroll
        for (int ni = 0; ni < 2; ni++)
            wmma::store_matrix_sync(zs + (mi * 16) * ZLD + nb + ni * 16,
                                    c[mi][ni], ZLD, wmma::mem_row_major);
    __syncthreads();

    float bias = (t < HD) ? __ldg(&bc2[t]) : __ldg(&bv2[t - HD]);
    float hw   = (t < HD) ? __ldg(&Wp[t])  : __ldg(&Wvh[t - HD]);
#pragma unroll 8
    for (int n = 0; n < 32; n++) {
        float v = zs[n * ZLD + t];
        zs[n * ZLD + t] = fmaxf(v + bias, 0.f) * hw;
    }
    __syncthreads();

    int task = t >> 2, l4 = t & 3;
    int n = task & 31, half = task >> 5;
    const float* row = zs + n * ZLD + half * HD + l4 * 32;
    float s = 0.f;
#pragma unroll
    for (int i = 0; i < 32; i++) s += row[i];
    s += __shfl_down_sync(0xffffffffu, s, 1);
    s += __shfl_down_sync(0xffffffffu, s, 2);
    int node = node0 + n;
    if (l4 == 0 && node < NN) {
        if (half == 0) out[node]      = s + __ldg(&bp[0]);
        else           out[NN + node] = s + __ldg(&bvh[0]);
    }
}

// ---------------- launch (kernel launches ONLY) ----------------
extern "C" void kernel_launch(void* const* d_in, const int* in_sizes, int n_in,
                              void* d_out, int out_size) {
    const float* x   = (const float*)d_in[0];
    const int*   ei  = (const int*)d_in[1];
    const float* Wc1 = (const float*)d_in[2];
    const float* bc1 = (const float*)d_in[3];
    const float* Wc2 = (const float*)d_in[4];
    const float* bc2 = (const float*)d_in[5];
    const float* Wp  = (const float*)d_in[6];
    const float* bp  = (const float*)d_in[7];
    const float* Wv1 = (const float*)d_in[8];
    const float* bv1 = (const float*)d_in[9];
    const float* Wv2 = (const float*)d_in[10];
    const float* bv2 = (const float*)d_in[11];
    const float* Wvh = (const float*)d_in[12];
    const float* bvh = (const float*)d_in[13];
    float* out = (float*)d_out;

    k_count <<<(EE + 255) / 256, 256>>>(ei, Wc2, Wv2);
    k_scan  <<<SCB, 256>>>();
    k_fill  <<<(EE + NN + 255) / 256, 256>>>(ei);

    k_layer1<<<(NN + 15) / 16, 256>>>(x, Wc1, Wv1, bc1, bv1);
    k_spmmh <<<(NN + 7) / 8, 256>>>();
    k_gemm2t<<<(NN + 31) / 32, 256>>>(bc2, bv2, Wp, Wvh, bp, bvh, out);
}

// round 13
// speedup vs baseline: 1.0720x; 1.0720x over previous
#include <cuda_runtime.h>
#include <cuda_fp16.h>
#include <mma.h>
#include <cstdint>

using namespace nvcuda;

#define NN 50000
#define EE 800000
#define IND 16
#define HD 128
#define WW 256          // fused width (policy 0..127, value 128..255)
#define SCB 49          // scan blocks
#define ZLD 264         // z/A tile leading dim (elements)

// ---------------- device scratch (static, no allocation; zero-initialized) ----
__device__ int    g_cnt[NN + 16];
__device__ int    g_cur[NN];
__device__ int    g_off[NN + 1];
__device__ int    g_bsum[64];
__device__ int2   g_edge[EE + NN];             // (src, norm-bits) per CSR slot
__device__ float  g_dis[NN];
__device__ __half g_xh[EE];                    // fp16 copy of x (NN*IND == EE)
__device__ __half g_w2h[WW * HD];              // fp16 fused [Wc2;Wv2]
__device__ __half g_h[(size_t)NN * WW];        // relu(layer1), fp16
__device__ __half g_aggh[(size_t)(NN + 32) * WW]; // A_norm @ h, fp16 (+pad rows)

// ---------------- graph prep ----------------
// g_cnt/g_cur zero on entry (zero-init statics; re-zeroed by k_layer1 each call)
__global__ void k_count(const int* __restrict__ ei,
                        const float* __restrict__ x,
                        const float* __restrict__ Wc2,
                        const float* __restrict__ Wv2) {
    int e = blockIdx.x * blockDim.x + threadIdx.x;
    if (e < EE) {
        atomicAdd(&g_cnt[ei[EE + e]], 1);
        g_xh[e] = __float2half(x[e]);          // fp16 copy of x (same extent)
    }
    // piggyback: fp16 weight conversion for the tensor-core gemm2
    if (e < WW * HD)
        g_w2h[e] = __float2half((e < HD * HD) ? Wc2[e] : Wv2[e - HD * HD]);
}

// stage A: per-block sums of c[i] = cnt[i]+1 over 1024-elem ranges
__global__ void k_scanA() {
    __shared__ int sred[256];
    int b = blockIdx.x, t = threadIdx.x;
    int i0 = (b * 256 + t) * 4;
    int s = 0;
    if (i0 < NN) {
        int4 c = *(const int4*)&g_cnt[i0];
        s = c.x + c.y + c.z + c.w + 4;
    }
    sred[t] = s;
    __syncthreads();
#pragma unroll
    for (int off = 128; off > 0; off >>= 1) {
        if (t < off) sred[t] += sred[t + off];
        __syncthreads();
    }
    if (t == 0) g_bsum[b] = sred[0];
}

// stage C: every block redundantly scans the 49 block sums, then rescans
__global__ void k_scanC() {
    __shared__ int ss[256];
    __shared__ int sb[64];
    int b = blockIdx.x, t = threadIdx.x;
    if (t < 32) {
        int v0 = (t < SCB) ? g_bsum[t] : 0;
        int v1 = (t + 32 < SCB) ? g_bsum[t + 32] : 0;
#pragma unroll
        for (int o = 1; o < 32; o <<= 1) {
            int u = __shfl_up_sync(0xffffffffu, v0, o);
            if (t >= o) v0 += u;
        }
        int tot0 = __shfl_sync(0xffffffffu, v0, 31);
#pragma unroll
        for (int o = 1; o < 32; o <<= 1) {
            int u = __shfl_up_sync(0xffffffffu, v1, o);
            if (t >= o) v1 += u;
        }
        sb[t] = v0;
        sb[t + 32] = v1 + tot0;
    }
    __syncthreads();
    int bpre = (b == 0) ? 0 : sb[b - 1];
    if (b == SCB - 1 && t == 0) g_off[NN] = sb[SCB - 1];

    int i0 = (b * 256 + t) * 4;
    int4 c = {0, 0, 0, 0};
    int s = 0;
    if (i0 < NN) {
        c = *(const int4*)&g_cnt[i0];
        c.x += 1; c.y += 1; c.z += 1; c.w += 1;
        s = c.x + c.y + c.z + c.w;
    }
    ss[t] = s;
    __syncthreads();
#pragma unroll
    for (int off = 1; off < 256; off <<= 1) {
        int u = (t >= off) ? ss[t - off] : 0;
        __syncthreads();
        ss[t] += u;
        __syncthreads();
    }
    int run = ss[t] - s + bpre;
    if (i0 < NN) {
        g_off[i0]     = run; g_dis[i0]     = rsqrtf((float)c.x); run += c.x;
        g_off[i0 + 1] = run; g_dis[i0 + 1] = rsqrtf((float)c.y); run += c.y;
        g_off[i0 + 2] = run; g_dis[i0 + 2] = rsqrtf((float)c.z); run += c.z;
        g_off[i0 + 3] = run; g_dis[i0 + 3] = rsqrtf((float)c.w);
    }
}

// fill CSR with packed (src, norm)
__global__ void k_fill(const int* __restrict__ ei) {
    int i = blockIdx.x * blockDim.x + threadIdx.x;
    if (i < EE) {
        int s = ei[i];
        int d = ei[EE + i];
        float nw = g_dis[s] * g_dis[d];
        int pos = g_off[d] + atomicAdd(&g_cur[d], 1);
        g_edge[pos] = make_int2(s, __float_as_int(nw));
    } else if (i < EE + NN) {
        int n = i - EE;
        float ds = g_dis[n];
        g_edge[g_off[n + 1] - 1] = make_int2(n, __float_as_int(ds * ds));
    }
}

// ---------------- shared fp16 accumulate helper ----------------
__device__ __forceinline__ void acc8(float* acc, float nw, uint4 v) {
    float2 p;
    p = __half22float2(*(const __half2*)&v.x);
    acc[0] = fmaf(nw, p.x, acc[0]); acc[1] = fmaf(nw, p.y, acc[1]);
    p = __half22float2(*(((const __half2*)&v.x) + 1));
    acc[2] = fmaf(nw, p.x, acc[2]); acc[3] = fmaf(nw, p.y, acc[3]);
    p = __half22float2(*(const __half2*)&v.z);
    acc[4] = fmaf(nw, p.x, acc[4]); acc[5] = fmaf(nw, p.y, acc[5]);
    p = __half22float2(*(((const __half2*)&v.z) + 1));
    acc[6] = fmaf(nw, p.x, acc[6]); acc[7] = fmaf(nw, p.y, acc[7]);
}

// ------- fused layer 1: 16 nodes/block -------
// gather phase: 2 lanes/edge (uint4 of fp16 x-row), 16 edges in flight/warp
// dense phase: thread t = fused output col; W1 amortized over 16 nodes
// also: re-zero g_cnt/g_cur for the next call
__global__ void __launch_bounds__(256) k_layer1(const float* __restrict__ Wc1,
                                                const float* __restrict__ Wv1,
                                                const float* __restrict__ bc1,
                                                const float* __restrict__ bv1) {
    __shared__ float xs[16][IND];
    int t = threadIdx.x, w = t >> 5, lane = t & 31;
    int node0 = blockIdx.x * 16;

    // counter cleanup for next call
    int gid = blockIdx.x * 256 + t;
    if (gid < NN) { g_cnt[gid] = 0; g_cur[gid] = 0; }
    else if (gid < NN + 16) g_cnt[gid] = 0;

    int slot = lane >> 1, part = lane & 1;     // 16 edge slots x 2 half-rows
#pragma unroll
    for (int q = 0; q < 2; q++) {
        int node = node0 + w * 2 + q;
        if (node < NN) {
            int jb = g_off[node], je = g_off[node + 1];
            float acc[8];
#pragma unroll
            for (int i = 0; i < 8; i++) acc[i] = 0.f;
            for (int j = jb + slot; j < je; j += 16) {
                int2 e = g_edge[j];
                uint4 xv = __ldg((const uint4*)(g_xh + e.x * IND) + part);
                acc8(acc, __int_as_float(e.y), xv);
            }
            // reduce across the 16 slots (lane stride 2 preserves part)
#pragma unroll
            for (int off = 16; off >= 2; off >>= 1) {
#pragma unroll
                for (int i = 0; i < 8; i++)
                    acc[i] += __shfl_down_sync(0xffffffffu, acc[i], off);
            }
            if (lane < 2) {                    // lane0: cols 0-7, lane1: 8-15
                *(float4*)&xs[w * 2 + q][lane * 8]     = make_float4(acc[0], acc[1], acc[2], acc[3]);
                *(float4*)&xs[w * 2 + q][lane * 8 + 4] = make_float4(acc[4], acc[5], acc[6], acc[7]);
            }
        }
    }
    __syncthreads();

    const float4* wr = (const float4*)((t < HD) ? (Wc1 + t * IND)
                                                : (Wv1 + (t - HD) * IND));
    float4 w0 = __ldg(&wr[0]), w1 = __ldg(&wr[1]);
    float4 w2 = __ldg(&wr[2]), w3 = __ldg(&wr[3]);
    float bias = (t < HD) ? __ldg(&bc1[t]) : __ldg(&bv1[t - HD]);
#pragma unroll
    for (int n = 0; n < 16; n++) {
        int node = node0 + n;
        if (node >= NN) break;
        float a = bias;
        a = fmaf(w0.x, xs[n][0],  a); a = fmaf(w0.y, xs[n][1],  a);
        a = fmaf(w0.z, xs[n][2],  a); a = fmaf(w0.w, xs[n][3],  a);
        a = fmaf(w1.x, xs[n][4],  a); a = fmaf(w1.y, xs[n][5],  a);
        a = fmaf(w1.z, xs[n][6],  a); a = fmaf(w1.w, xs[n][7],  a);
        a = fmaf(w2.x, xs[n][8],  a); a = fmaf(w2.y, xs[n][9],  a);
        a = fmaf(w2.z, xs[n][10], a); a = fmaf(w2.w, xs[n][11], a);
        a = fmaf(w3.x, xs[n][12], a); a = fmaf(w3.y, xs[n][13], a);
        a = fmaf(w3.z, xs[n][14], a); a = fmaf(w3.w, xs[n][15], a);
        g_h[(size_t)node * WW + t] = __float2half(fmaxf(a, 0.f));
    }
}

// ---------------- SpMM on h (256-wide, fp16 gather): aggh = A_norm @ h ------
__global__ void __launch_bounds__(256) k_spmmh() {
    int w = threadIdx.x >> 5, lane = threadIdx.x & 31;
    int node = blockIdx.x * 8 + w;
    if (node >= NN) return;
    int jb = g_off[node], je = g_off[node + 1];
    const __half* hp = g_h + (size_t)lane * 8;
    float acc[8];
#pragma unroll
    for (int i = 0; i < 8; i++) acc[i] = 0.f;
    int j = jb;
    for (; j + 4 <= je; j += 4) {
        int2 e0 = g_edge[j],     e1 = g_edge[j + 1];
        int2 e2 = g_edge[j + 2], e3 = g_edge[j + 3];
        uint4 v0 = __ldg((const uint4*)(hp + (size_t)e0.x * WW));
        uint4 v1 = __ldg((const uint4*)(hp + (size_t)e1.x * WW));
        uint4 v2 = __ldg((const uint4*)(hp + (size_t)e2.x * WW));
        uint4 v3 = __ldg((const uint4*)(hp + (size_t)e3.x * WW));
        acc8(acc, __int_as_float(e0.y), v0);
        acc8(acc, __int_as_float(e1.y), v1);
        acc8(acc, __int_as_float(e2.y), v2);
        acc8(acc, __int_as_float(e3.y), v3);
    }
    for (; j < je; j++) {
        int2 e = g_edge[j];
        uint4 v = __ldg((const uint4*)(hp + (size_t)e.x * WW));
        acc8(acc, __int_as_float(e.y), v);
    }
    __half2 ho[4];
#pragma unroll
    for (int i = 0; i < 4; i++)
        ho[i] = __floats2half2_rn(acc[i * 2], acc[i * 2 + 1]);
    *(uint4*)(g_aggh + (size_t)node * WW + lane * 8) = *(uint4*)ho;
}

// ---------------- dense layer 2 + heads (tensor cores) ----------------
__global__ void __launch_bounds__(256)
k_gemm2t(const float* __restrict__ bc2, const float* __restrict__ bv2,
         const float* __restrict__ Wp,  const float* __restrict__ Wvh,
         const float* __restrict__ bp,  const float* __restrict__ bvh,
         float* __restrict__ out) {
    __shared__ __align__(16) char sbuf[32 * ZLD * 4];   // 33.8 KB
    __half* As = (__half*)sbuf;                         // [32][ZLD] halves
    float*  zs = (float*)sbuf;                          // [32][ZLD] floats
    int t = threadIdx.x, warp = t >> 5;
    int node0 = blockIdx.x * 32;

    {
        const uint4* src = (const uint4*)(g_aggh + (size_t)node0 * WW);
        uint4* dst = (uint4*)As;
#pragma unroll
        for (int i = 0; i < 4; i++) {
            int idx = t + i * 256;
            int m = idx >> 5, c8 = idx & 31;
            dst[m * (ZLD / 8) + c8] = src[m * (WW / 8) + c8];
        }
    }
    __syncthreads();

    int nb = warp * 32;
    int kb = (warp < 4) ? 0 : HD;
    const __half* Bbase = g_w2h + nb * HD;

    wmma::fragment<wmma::accumulator, 16, 16, 16, float> c[2][2];
#pragma unroll
    for (int mi = 0; mi < 2; mi++)
#pragma unroll
        for (int ni = 0; ni < 2; ni++) wmma::fill_fragment(c[mi][ni], 0.f);

#pragma unroll
    for (int k = 0; k < HD; k += 16) {
        wmma::fragment<wmma::matrix_a, 16, 16, 16, __half, wmma::row_major> a0, a1;
        wmma::load_matrix_sync(a0, As + kb + k, ZLD);
        wmma::load_matrix_sync(a1, As + 16 * ZLD + kb + k, ZLD);
        wmma::fragment<wmma::matrix_b, 16, 16, 16, __half, wmma::col_major> b0, b1;
        wmma::load_matrix_sync(b0, Bbase + k, HD);
        wmma::load_matrix_sync(b1, Bbase + 16 * HD + k, HD);
        wmma::mma_sync(c[0][0], a0, b0, c[0][0]);
        wmma::mma_sync(c[0][1], a0, b1, c[0][1]);
        wmma::mma_sync(c[1][0], a1, b0, c[1][0]);
        wmma::mma_sync(c[1][1], a1, b1, c[1][1]);
    }
    __syncthreads();

#pragma unroll
    for (int mi = 0; mi < 2; mi++)
#pragma unroll
        for (int ni = 0; ni < 2; ni++)
            wmma::store_matrix_sync(zs + (mi * 16) * ZLD + nb + ni * 16,
                                    c[mi][ni], ZLD, wmma::mem_row_major);
    __syncthreads();

    float bias = (t < HD) ? __ldg(&bc2[t]) : __ldg(&bv2[t - HD]);
    float hw   = (t < HD) ? __ldg(&Wp[t])  : __ldg(&Wvh[t - HD]);
#pragma unroll 8
    for (int n = 0; n < 32; n++) {
        float v = zs[n * ZLD + t];
        zs[n * ZLD + t] = fmaxf(v + bias, 0.f) * hw;
    }
    __syncthreads();

    int task = t >> 2, l4 = t & 3;
    int n = task & 31, half = task >> 5;
    const float* row = zs + n * ZLD + half * HD + l4 * 32;
    float s = 0.f;
#pragma unroll
    for (int i = 0; i < 32; i++) s += row[i];
    s += __shfl_down_sync(0xffffffffu, s, 1);
    s += __shfl_down_sync(0xffffffffu, s, 2);
    int node = node0 + n;
    if (l4 == 0 && node < NN) {
        if (half == 0) out[node]      = s + __ldg(&bp[0]);
        else           out[NN + node] = s + __ldg(&bvh[0]);
    }
}

// ---------------- launch (kernel launches ONLY) ----------------
extern "C" void kernel_launch(void* const* d_in, const int* in_sizes, int n_in,
                              void* d_out, int out_size) {
    const float* x   = (const float*)d_in[0];
    const int*   ei  = (const int*)d_in[1];
    const float* Wc1 = (const float*)d_in[2];
    const float* bc1 = (const float*)d_in[3];
    const float* Wc2 = (const float*)d_in[4];
    const float* bc2 = (const float*)d_in[5];
    const float* Wp  = (const float*)d_in[6];
    const float* bp  = (const float*)d_in[7];
    const float* Wv1 = (const float*)d_in[8];
    const float* bv1 = (const float*)d_in[9];
    const float* Wv2 = (const float*)d_in[10];
    const float* bv2 = (const float*)d_in[11];
    const float* Wvh = (const float*)d_in[12];
    const float* bvh = (const float*)d_in[13];
    float* out = (float*)d_out;

    k_count <<<(EE + 255) / 256, 256>>>(ei, x, Wc2, Wv2);
    k_scanA <<<SCB, 256>>>();
    k_scanC <<<SCB, 256>>>();
    k_fill  <<<(EE + NN + 255) / 256, 256>>>(ei);

    k_layer1<<<(NN + 15) / 16, 256>>>(Wc1, Wv1, bc1, bv1);
    k_spmmh <<<(NN + 7) / 8, 256>>>();
    k_gemm2t<<<(NN + 31) / 32, 256>>>(bc2, bv2, Wp, Wvh, bp, bvh, out);
}

// round 14
// speedup vs baseline: 1.1557x; 1.0781x over previous
#include <cuda_runtime.h>
#include <cuda_fp16.h>
#include <mma.h>
#include <cstdint>

using namespace nvcuda;

#define NN 50000
#define EE 800000
#define IND 16
#define HD 128
#define WW 256          // fused width (policy 0..127, value 128..255)
#define CAP 96          // bucket capacity per node (deg ~ Poisson(16))
#define ZLD 264         // z/A tile leading dim (elements)

// ---------------- device scratch (static, no allocation; zero-initialized) ----
__device__ int    g_cnt[NN];                   // zero on entry; re-zeroed by k_layer1
__device__ int    g_deg[NN];
__device__ int    g_src[(size_t)NN * CAP];     // bucket CSR (row base = node*CAP)
__device__ float  g_dis[NN];
__device__ __half g_xh[EE];                    // fp16 copy of x (NN*IND == EE)
__device__ __half g_w2h[WW * HD];              // fp16 fused [Wc2;Wv2]
__device__ __half g_h[(size_t)NN * WW];        // relu(layer1), fp16
__device__ __half g_aggh[(size_t)(NN + 32) * WW]; // A_norm @ h, fp16 (+pad rows)

// ---------------- graph build: ONE pass (atomic slot + scatter) ----------------
__global__ void k_build(const int* __restrict__ ei,
                        const float* __restrict__ x,
                        const float* __restrict__ Wc2,
                        const float* __restrict__ Wv2) {
    int e = blockIdx.x * blockDim.x + threadIdx.x;
    if (e < EE) {
        int d = ei[EE + e];
        int r = atomicAdd(&g_cnt[d], 1);
        g_src[(size_t)d * CAP + r] = ei[e];
        g_xh[e] = __float2half(x[e]);          // fp16 copy of x (same extent)
    }
    if (e < WW * HD)
        g_w2h[e] = __float2half((e < HD * HD) ? Wc2[e] : Wv2[e - HD * HD]);
}

// self-loop + degree + dis (replaces the whole scan pipeline)
__global__ void k_dis() {
    int i = blockIdx.x * blockDim.x + threadIdx.x;
    if (i < NN) {
        int c = g_cnt[i];
        g_src[(size_t)i * CAP + c] = i;        // self-loop in last slot
        g_deg[i] = c + 1;
        g_dis[i] = rsqrtf((float)(c + 1));
    }
}

// ---------------- shared fp16 accumulate helper ----------------
__device__ __forceinline__ void acc8(float* acc, float nw, uint4 v) {
    float2 p;
    p = __half22float2(*(const __half2*)&v.x);
    acc[0] = fmaf(nw, p.x, acc[0]); acc[1] = fmaf(nw, p.y, acc[1]);
    p = __half22float2(*(((const __half2*)&v.x) + 1));
    acc[2] = fmaf(nw, p.x, acc[2]); acc[3] = fmaf(nw, p.y, acc[3]);
    p = __half22float2(*(const __half2*)&v.z);
    acc[4] = fmaf(nw, p.x, acc[4]); acc[5] = fmaf(nw, p.y, acc[5]);
    p = __half22float2(*(((const __half2*)&v.z) + 1));
    acc[6] = fmaf(nw, p.x, acc[6]); acc[7] = fmaf(nw, p.y, acc[7]);
}

// ------- fused layer 1: 16 nodes/block -------
// gather phase: 2 lanes/edge (uint4 of fp16 x-row), 16 edges in flight/warp
// dense phase: thread t = fused output col; W1 amortized over 16 nodes
// also: re-zero g_cnt for the next call
__global__ void __launch_bounds__(256) k_layer1(const float* __restrict__ Wc1,
                                                const float* __restrict__ Wv1,
                                                const float* __restrict__ bc1,
                                                const float* __restrict__ bv1) {
    __shared__ float xs[16][IND];
    int t = threadIdx.x, w = t >> 5, lane = t & 31;
    int node0 = blockIdx.x * 16;

    // counter cleanup for next call
    int gid = blockIdx.x * 256 + t;
    if (gid < NN) g_cnt[gid] = 0;

    int slot = lane >> 1, part = lane & 1;     // 16 edge slots x 2 half-rows
#pragma unroll
    for (int q = 0; q < 2; q++) {
        int node = node0 + w * 2 + q;
        if (node < NN) {
            float di = g_dis[node];
            int jb = node * CAP, je = jb + g_deg[node];
            float acc[8];
#pragma unroll
            for (int i = 0; i < 8; i++) acc[i] = 0.f;
            for (int j = jb + slot; j < je; j += 16) {
                int s = g_src[j];
                float nw = di * g_dis[s];
                uint4 xv = __ldg((const uint4*)(g_xh + s * IND) + part);
                acc8(acc, nw, xv);
            }
            // reduce across the 16 slots (lane stride 2 preserves part)
#pragma unroll
            for (int off = 16; off >= 2; off >>= 1) {
#pragma unroll
                for (int i = 0; i < 8; i++)
                    acc[i] += __shfl_down_sync(0xffffffffu, acc[i], off);
            }
            if (lane < 2) {                    // lane0: cols 0-7, lane1: 8-15
                *(float4*)&xs[w * 2 + q][lane * 8]     = make_float4(acc[0], acc[1], acc[2], acc[3]);
                *(float4*)&xs[w * 2 + q][lane * 8 + 4] = make_float4(acc[4], acc[5], acc[6], acc[7]);
            }
        }
    }
    __syncthreads();

    const float4* wr = (const float4*)((t < HD) ? (Wc1 + t * IND)
                                                : (Wv1 + (t - HD) * IND));
    float4 w0 = __ldg(&wr[0]), w1 = __ldg(&wr[1]);
    float4 w2 = __ldg(&wr[2]), w3 = __ldg(&wr[3]);
    float bias = (t < HD) ? __ldg(&bc1[t]) : __ldg(&bv1[t - HD]);
#pragma unroll
    for (int n = 0; n < 16; n++) {
        int node = node0 + n;
        if (node >= NN) break;
        float a = bias;
        a = fmaf(w0.x, xs[n][0],  a); a = fmaf(w0.y, xs[n][1],  a);
        a = fmaf(w0.z, xs[n][2],  a); a = fmaf(w0.w, xs[n][3],  a);
        a = fmaf(w1.x, xs[n][4],  a); a = fmaf(w1.y, xs[n][5],  a);
        a = fmaf(w1.z, xs[n][6],  a); a = fmaf(w1.w, xs[n][7],  a);
        a = fmaf(w2.x, xs[n][8],  a); a = fmaf(w2.y, xs[n][9],  a);
        a = fmaf(w2.z, xs[n][10], a); a = fmaf(w2.w, xs[n][11], a);
        a = fmaf(w3.x, xs[n][12], a); a = fmaf(w3.y, xs[n][13], a);
        a = fmaf(w3.z, xs[n][14], a); a = fmaf(w3.w, xs[n][15], a);
        g_h[(size_t)node * WW + t] = __float2half(fmaxf(a, 0.f));
    }
}

// ---------------- SpMM on h (256-wide, fp16 gather): aggh = A_norm @ h ------
__global__ void __launch_bounds__(256) k_spmmh() {
    int w = threadIdx.x >> 5, lane = threadIdx.x & 31;
    int node = blockIdx.x * 8 + w;
    if (node >= NN) return;
    float di = g_dis[node];
    int jb = node * CAP;                       // 384B-aligned row base
    int deg = g_deg[node];
    const __half* hp = g_h + (size_t)lane * 8;
    float acc[8];
#pragma unroll
    for (int i = 0; i < 8; i++) acc[i] = 0.f;
    int j = 0;
    for (; j + 4 <= deg; j += 4) {
        int4 s4 = *(const int4*)&g_src[jb + j];   // one aligned LDG.128
        float n0 = di * g_dis[s4.x], n1 = di * g_dis[s4.y];
        float n2 = di * g_dis[s4.z], n3 = di * g_dis[s4.w];
        uint4 v0 = __ldg((const uint4*)(hp + (size_t)s4.x * WW));
        uint4 v1 = __ldg((const uint4*)(hp + (size_t)s4.y * WW));
        uint4 v2 = __ldg((const uint4*)(hp + (size_t)s4.z * WW));
        uint4 v3 = __ldg((const uint4*)(hp + (size_t)s4.w * WW));
        acc8(acc, n0, v0);
        acc8(acc, n1, v1);
        acc8(acc, n2, v2);
        acc8(acc, n3, v3);
    }
    for (; j < deg; j++) {
        int s = g_src[jb + j];
        float nw = di * g_dis[s];
        uint4 v = __ldg((const uint4*)(hp + (size_t)s * WW));
        acc8(acc, nw, v);
    }
    __half2 ho[4];
#pragma unroll
    for (int i = 0; i < 4; i++)
        ho[i] = __floats2half2_rn(acc[i * 2], acc[i * 2 + 1]);
    *(uint4*)(g_aggh + (size_t)node * WW + lane * 8) = *(uint4*)ho;
}

// ---------------- dense layer 2 + heads (tensor cores) ----------------
__global__ void __launch_bounds__(256)
k_gemm2t(const float* __restrict__ bc2, const float* __restrict__ bv2,
         const float* __restrict__ Wp,  const float* __restrict__ Wvh,
         const float* __restrict__ bp,  const float* __restrict__ bvh,
         float* __restrict__ out) {
    __shared__ __align__(16) char sbuf[32 * ZLD * 4];   // 33.8 KB
    __half* As = (__half*)sbuf;                         // [32][ZLD] halves
    float*  zs = (float*)sbuf;                          // [32][ZLD] floats
    int t = threadIdx.x, warp = t >> 5;
    int node0 = blockIdx.x * 32;

    {
        const uint4* src = (const uint4*)(g_aggh + (size_t)node0 * WW);
        uint4* dst = (uint4*)As;
#pragma unroll
        for (int i = 0; i < 4; i++) {
            int idx = t + i * 256;
            int m = idx >> 5, c8 = idx & 31;
            dst[m * (ZLD / 8) + c8] = src[m * (WW / 8) + c8];
        }
    }
    __syncthreads();

    int nb = warp * 32;
    int kb = (warp < 4) ? 0 : HD;
    const __half* Bbase = g_w2h + nb * HD;

    wmma::fragment<wmma::accumulator, 16, 16, 16, float> c[2][2];
#pragma unroll
    for (int mi = 0; mi < 2; mi++)
#pragma unroll
        for (int ni = 0; ni < 2; ni++) wmma::fill_fragment(c[mi][ni], 0.f);

#pragma unroll
    for (int k = 0; k < HD; k += 16) {
        wmma::fragment<wmma::matrix_a, 16, 16, 16, __half, wmma::row_major> a0, a1;
        wmma::load_matrix_sync(a0, As + kb + k, ZLD);
        wmma::load_matrix_sync(a1, As + 16 * ZLD + kb + k, ZLD);
        wmma::fragment<wmma::matrix_b, 16, 16, 16, __half, wmma::col_major> b0, b1;
        wmma::load_matrix_sync(b0, Bbase + k, HD);
        wmma::load_matrix_sync(b1, Bbase + 16 * HD + k, HD);
        wmma::mma_sync(c[0][0], a0, b0, c[0][0]);
        wmma::mma_sync(c[0][1], a0, b1, c[0][1]);
        wmma::mma_sync(c[1][0], a1, b0, c[1][0]);
        wmma::mma_sync(c[1][1], a1, b1, c[1][1]);
    }
    __syncthreads();

#pragma unroll
    for (int mi = 0; mi < 2; mi++)
#pragma unroll
        for (int ni = 0; ni < 2; ni++)
            wmma::store_matrix_sync(zs + (mi * 16) * ZLD + nb + ni * 16,
                                    c[mi][ni], ZLD, wmma::mem_row_major);
    __syncthreads();

    float bias = (t < HD) ? __ldg(&bc2[t]) : __ldg(&bv2[t - HD]);
    float hw   = (t < HD) ? __ldg(&Wp[t])  : __ldg(&Wvh[t - HD]);
#pragma unroll 8
    for (int n = 0; n < 32; n++) {
        float v = zs[n * ZLD + t];
        zs[n * ZLD + t] = fmaxf(v + bias, 0.f) * hw;
    }
    __syncthreads();

    int task = t >> 2, l4 = t & 3;
    int n = task & 31, half = task >> 5;
    const float* row = zs + n * ZLD + half * HD + l4 * 32;
    float s = 0.f;
#pragma unroll
    for (int i = 0; i < 32; i++) s += row[i];
    s += __shfl_down_sync(0xffffffffu, s, 1);
    s += __shfl_down_sync(0xffffffffu, s, 2);
    int node = node0 + n;
    if (l4 == 0 && node < NN) {
        if (half == 0) out[node]      = s + __ldg(&bp[0]);
        else           out[NN + node] = s + __ldg(&bvh[0]);
    }
}

// ---------------- launch (kernel launches ONLY) ----------------
extern "C" void kernel_launch(void* const* d_in, const int* in_sizes, int n_in,
                              void* d_out, int out_size) {
    const float* x   = (const float*)d_in[0];
    const int*   ei  = (const int*)d_in[1];
    const float* Wc1 = (const float*)d_in[2];
    const float* bc1 = (const float*)d_in[3];
    const float* Wc2 = (const float*)d_in[4];
    const float* bc2 = (const float*)d_in[5];
    const float* Wp  = (const float*)d_in[6];
    const float* bp  = (const float*)d_in[7];
    const float* Wv1 = (const float*)d_in[8];
    const float* bv1 = (const float*)d_in[9];
    const float* Wv2 = (const float*)d_in[10];
    const float* bv2 = (const float*)d_in[11];
    const float* Wvh = (const float*)d_in[12];
    const float* bvh = (const float*)d_in[13];
    float* out = (float*)d_out;

    k_build <<<(EE + 255) / 256, 256>>>(ei, x, Wc2, Wv2);
    k_dis   <<<(NN + 255) / 256, 256>>>();
    k_layer1<<<(NN + 15) / 16, 256>>>(Wc1, Wv1, bc1, bv1);
    k_spmmh <<<(NN + 7) / 8, 256>>>();
    k_gemm2t<<<(NN + 31) / 32, 256>>>(bc2, bv2, Wp, Wvh, bp, bvh, out);
}

// round 15
// speedup vs baseline: 1.2334x; 1.0672x over previous
#include <cuda_runtime.h>
#include <cuda_fp16.h>
#include <mma.h>
#include <cstdint>

using namespace nvcuda;

#define NN 50000
#define EE 800000
#define IND 16
#define HD 128
#define WW 256          // fused width (policy 0..127, value 128..255)
#define CAP 96          // bucket capacity per node (deg ~ Poisson(16))
#define ZLD 264         // z/A tile leading dim (elements)

// ---------------- device scratch (static, no allocation; zero-initialized) ----
__device__ int    g_cnt[NN];                   // zero on entry; re-zeroed by k_layer1
__device__ int    g_deg[NN];
__device__ int    g_src[(size_t)NN * CAP];     // bucket CSR (row base = node*CAP)
__device__ float  g_dis[NN];
__device__ __half g_xh[EE];                    // fp16 dis[s]*x[s]  (NN*IND == EE)
__device__ __half g_w2h[WW * HD];              // fp16 fused [Wc2;Wv2]
__device__ __half g_h[(size_t)NN * WW];        // dis[n]*relu(layer1), fp16
__device__ __half g_aggh[(size_t)(NN + 32) * WW]; // A_norm @ h, fp16 (+pad rows)

// ---------------- graph build: ONE pass (atomic slot + scatter) ----------------
__global__ void k_build(const int* __restrict__ ei,
                        const float* __restrict__ Wc2,
                        const float* __restrict__ Wv2) {
    int e = blockIdx.x * blockDim.x + threadIdx.x;
    if (e < EE) {
        int d = ei[EE + e];
        int r = atomicAdd(&g_cnt[d], 1);
        g_src[(size_t)d * CAP + r] = ei[e];
    }
    if (e < WW * HD)
        g_w2h[e] = __float2half((e < HD * HD) ? Wc2[e] : Wv2[e - HD * HD]);
}

// self-loop + degree + dis; also writes xh = half(dis * x) row-wise
__global__ void k_dis(const float* __restrict__ x) {
    int i = blockIdx.x * blockDim.x + threadIdx.x;
    if (i < NN) {
        int c = g_cnt[i];
        g_src[(size_t)i * CAP + c] = i;        // self-loop in last slot
        g_deg[i] = c + 1;
        float di = rsqrtf((float)(c + 1));
        g_dis[i] = di;
        const float* xr = x + i * IND;
        __half2 o[8];
#pragma unroll
        for (int k = 0; k < 8; k++)
            o[k] = __floats2half2_rn(di * xr[k * 2], di * xr[k * 2 + 1]);
        *(uint4*)(g_xh + i * IND)     = *(uint4*)&o[0];
        *(uint4*)(g_xh + i * IND + 8) = *(uint4*)&o[4];
    }
}

// ---------------- shared fp16 sum helper (pure add, no weight) ----------------
__device__ __forceinline__ void sum8(float* acc, uint4 v) {
    float2 p;
    p = __half22float2(*(const __half2*)&v.x);
    acc[0] += p.x; acc[1] += p.y;
    p = __half22float2(*(((const __half2*)&v.x) + 1));
    acc[2] += p.x; acc[3] += p.y;
    p = __half22float2(*(const __half2*)&v.z);
    acc[4] += p.x; acc[5] += p.y;
    p = __half22float2(*(((const __half2*)&v.z) + 1));
    acc[6] += p.x; acc[7] += p.y;
}

// ------- fused layer 1: 16 nodes/block -------
// gather phase: 2 lanes/edge (uint4 of pre-scaled fp16 x-row), pure sum
// dense phase: thread t = fused output col; W1 amortized over 16 nodes
// also: re-zero g_cnt for the next call
__global__ void __launch_bounds__(256) k_layer1(const float* __restrict__ Wc1,
                                                const float* __restrict__ Wv1,
                                                const float* __restrict__ bc1,
                                                const float* __restrict__ bv1) {
    __shared__ float xs[16][IND];
    int t = threadIdx.x, w = t >> 5, lane = t & 31;
    int node0 = blockIdx.x * 16;

    // counter cleanup for next call
    int gid = blockIdx.x * 256 + t;
    if (gid < NN) g_cnt[gid] = 0;

    int slot = lane >> 1, part = lane & 1;     // 16 edge slots x 2 half-rows
#pragma unroll
    for (int q = 0; q < 2; q++) {
        int node = node0 + w * 2 + q;
        if (node < NN) {
            int jb = node * CAP, je = jb + g_deg[node];
            float acc[8];
#pragma unroll
            for (int i = 0; i < 8; i++) acc[i] = 0.f;
            for (int j = jb + slot; j < je; j += 16) {
                int s = g_src[j];
                uint4 xv = __ldg((const uint4*)(g_xh + s * IND) + part);
                sum8(acc, xv);
            }
            // reduce across the 16 slots (lane stride 2 preserves part)
#pragma unroll
            for (int off = 16; off >= 2; off >>= 1) {
#pragma unroll
                for (int i = 0; i < 8; i++)
                    acc[i] += __shfl_down_sync(0xffffffffu, acc[i], off);
            }
            if (lane < 2) {                    // apply dis[node] once here
                float di = g_dis[node];
                *(float4*)&xs[w * 2 + q][lane * 8] =
                    make_float4(di * acc[0], di * acc[1], di * acc[2], di * acc[3]);
                *(float4*)&xs[w * 2 + q][lane * 8 + 4] =
                    make_float4(di * acc[4], di * acc[5], di * acc[6], di * acc[7]);
            }
        }
    }
    __syncthreads();

    const float4* wr = (const float4*)((t < HD) ? (Wc1 + t * IND)
                                                : (Wv1 + (t - HD) * IND));
    float4 w0 = __ldg(&wr[0]), w1 = __ldg(&wr[1]);
    float4 w2 = __ldg(&wr[2]), w3 = __ldg(&wr[3]);
    float bias = (t < HD) ? __ldg(&bc1[t]) : __ldg(&bv1[t - HD]);
#pragma unroll
    for (int n = 0; n < 16; n++) {
        int node = node0 + n;
        if (node >= NN) break;
        float a = bias;
        a = fmaf(w0.x, xs[n][0],  a); a = fmaf(w0.y, xs[n][1],  a);
        a = fmaf(w0.z, xs[n][2],  a); a = fmaf(w0.w, xs[n][3],  a);
        a = fmaf(w1.x, xs[n][4],  a); a = fmaf(w1.y, xs[n][5],  a);
        a = fmaf(w1.z, xs[n][6],  a); a = fmaf(w1.w, xs[n][7],  a);
        a = fmaf(w2.x, xs[n][8],  a); a = fmaf(w2.y, xs[n][9],  a);
        a = fmaf(w2.z, xs[n][10], a); a = fmaf(w2.w, xs[n][11], a);
        a = fmaf(w3.x, xs[n][12], a); a = fmaf(w3.y, xs[n][13], a);
        a = fmaf(w3.z, xs[n][14], a); a = fmaf(w3.w, xs[n][15], a);
        // store pre-scaled by dis[node] for the next aggregation
        g_h[(size_t)node * WW + t] = __float2half(g_dis[node] * fmaxf(a, 0.f));
    }
}

// ---------------- SpMM on h (256-wide, fp16 pure-sum gather) ----------------
__global__ void __launch_bounds__(256, 6) k_spmmh() {
    int w = threadIdx.x >> 5, lane = threadIdx.x & 31;
    int node = blockIdx.x * 8 + w;
    if (node >= NN) return;
    int jb = node * CAP;                       // 384B-aligned row base
    int deg = g_deg[node];
    const __half* hp = g_h + (size_t)lane * 8;
    float acc[8];
#pragma unroll
    for (int i = 0; i < 8; i++) acc[i] = 0.f;
    int j = 0;
    for (; j + 4 <= deg; j += 4) {
        int4 s4 = *(const int4*)&g_src[jb + j];   // one aligned LDG.128
        uint4 v0 = __ldg((const uint4*)(hp + (size_t)s4.x * WW));
        uint4 v1 = __ldg((const uint4*)(hp + (size_t)s4.y * WW));
        uint4 v2 = __ldg((const uint4*)(hp + (size_t)s4.z * WW));
        uint4 v3 = __ldg((const uint4*)(hp + (size_t)s4.w * WW));
        sum8(acc, v0);
        sum8(acc, v1);
        sum8(acc, v2);
        sum8(acc, v3);
    }
    for (; j < deg; j++) {
        int s = g_src[jb + j];
        uint4 v = __ldg((const uint4*)(hp + (size_t)s * WW));
        sum8(acc, v);
    }
    float di = g_dis[node];
    __half2 ho[4];
#pragma unroll
    for (int i = 0; i < 4; i++)
        ho[i] = __floats2half2_rn(di * acc[i * 2], di * acc[i * 2 + 1]);
    *(uint4*)(g_aggh + (size_t)node * WW + lane * 8) = *(uint4*)ho;
}

// ---------------- dense layer 2 + heads (tensor cores) ----------------
__global__ void __launch_bounds__(256)
k_gemm2t(const float* __restrict__ bc2, const float* __restrict__ bv2,
         const float* __restrict__ Wp,  const float* __restrict__ Wvh,
         const float* __restrict__ bp,  const float* __restrict__ bvh,
         float* __restrict__ out) {
    __shared__ __align__(16) char sbuf[32 * ZLD * 4];   // 33.8 KB
    __half* As = (__half*)sbuf;                         // [32][ZLD] halves
    float*  zs = (float*)sbuf;                          // [32][ZLD] floats
    int t = threadIdx.x, warp = t >> 5;
    int node0 = blockIdx.x * 32;

    {
        const uint4* src = (const uint4*)(g_aggh + (size_t)node0 * WW);
        uint4* dst = (uint4*)As;
#pragma unroll
        for (int i = 0; i < 4; i++) {
            int idx = t + i * 256;
            int m = idx >> 5, c8 = idx & 31;
            dst[m * (ZLD / 8) + c8] = src[m * (WW / 8) + c8];
        }
    }
    __syncthreads();

    int nb = warp * 32;
    int kb = (warp < 4) ? 0 : HD;
    const __half* Bbase = g_w2h + nb * HD;

    wmma::fragment<wmma::accumulator, 16, 16, 16, float> c[2][2];
#pragma unroll
    for (int mi = 0; mi < 2; mi++)
#pragma unroll
        for (int ni = 0; ni < 2; ni++) wmma::fill_fragment(c[mi][ni], 0.f);

#pragma unroll
    for (int k = 0; k < HD; k += 16) {
        wmma::fragment<wmma::matrix_a, 16, 16, 16, __half, wmma::row_major> a0, a1;
        wmma::load_matrix_sync(a0, As + kb + k, ZLD);
        wmma::load_matrix_sync(a1, As + 16 * ZLD + kb + k, ZLD);
        wmma::fragment<wmma::matrix_b, 16, 16, 16, __half, wmma::col_major> b0, b1;
        wmma::load_matrix_sync(b0, Bbase + k, HD);
        wmma::load_matrix_sync(b1, Bbase + 16 * HD + k, HD);
        wmma::mma_sync(c[0][0], a0, b0, c[0][0]);
        wmma::mma_sync(c[0][1], a0, b1, c[0][1]);
        wmma::mma_sync(c[1][0], a1, b0, c[1][0]);
        wmma::mma_sync(c[1][1], a1, b1, c[1][1]);
    }
    __syncthreads();

#pragma unroll
    for (int mi = 0; mi < 2; mi++)
#pragma unroll
        for (int ni = 0; ni < 2; ni++)
            wmma::store_matrix_sync(zs + (mi * 16) * ZLD + nb + ni * 16,
                                    c[mi][ni], ZLD, wmma::mem_row_major);
    __syncthreads();

    float bias = (t < HD) ? __ldg(&bc2[t]) : __ldg(&bv2[t - HD]);
    float hw   = (t < HD) ? __ldg(&Wp[t])  : __ldg(&Wvh[t - HD]);
#pragma unroll 8
    for (int n = 0; n < 32; n++) {
        float v = zs[n * ZLD + t];
        zs[n * ZLD + t] = fmaxf(v + bias, 0.f) * hw;
    }
    __syncthreads();

    int task = t >> 2, l4 = t & 3;
    int n = task & 31, half = task >> 5;
    const float* row = zs + n * ZLD + half * HD + l4 * 32;
    float s = 0.f;
#pragma unroll
    for (int i = 0; i < 32; i++) s += row[i];
    s += __shfl_down_sync(0xffffffffu, s, 1);
    s += __shfl_down_sync(0xffffffffu, s, 2);
    int node = node0 + n;
    if (l4 == 0 && node < NN) {
        if (half == 0) out[node]      = s + __ldg(&bp[0]);
        else           out[NN + node] = s + __ldg(&bvh[0]);
    }
}

// ---------------- launch (kernel launches ONLY) ----------------
extern "C" void kernel_launch(void* const* d_in, const int* in_sizes, int n_in,
                              void* d_out, int out_size) {
    const float* x   = (const float*)d_in[0];
    const int*   ei  = (const int*)d_in[1];
    const float* Wc1 = (const float*)d_in[2];
    const float* bc1 = (const float*)d_in[3];
    const float* Wc2 = (const float*)d_in[4];
    const float* bc2 = (const float*)d_in[5];
    const float* Wp  = (const float*)d_in[6];
    const float* bp  = (const float*)d_in[7];
    const float* Wv1 = (const float*)d_in[8];
    const float* bv1 = (const float*)d_in[9];
    const float* Wv2 = (const float*)d_in[10];
    const float* bv2 = (const float*)d_in[11];
    const float* Wvh = (const float*)d_in[12];
    const float* bvh = (const float*)d_in[13];
    float* out = (float*)d_out;

    k_build <<<(EE + 255) / 256, 256>>>(ei, Wc2, Wv2);
    k_dis   <<<(NN + 255) / 256, 256>>>(x);
    k_layer1<<<(NN + 15) / 16, 256>>>(Wc1, Wv1, bc1, bv1);
    k_spmmh <<<(NN + 7) / 8, 256>>>();
    k_gemm2t<<<(NN + 31) / 32, 256>>>(bc2, bv2, Wp, Wvh, bp, bvh, out);
}

// round 16
// speedup vs baseline: 1.2549x; 1.0174x over previous
#include <cuda_runtime.h>
#include <cuda_fp16.h>
#include <mma.h>
#include <cstdint>

using namespace nvcuda;

#define NN 50000
#define EE 800000
#define IND 16
#define HD 128
#define WW 256          // fused width (policy 0..127, value 128..255)
#define CAP 96          // bucket capacity per node (deg ~ Poisson(16))
#define ZLD 264         // z/A tile leading dim (elements)

// ---------------- device scratch (static, no allocation; zero-initialized) ----
__device__ int    g_cnt[NN];                   // zero on entry; re-zeroed by k_layer1
__device__ int    g_deg[NN];
__device__ int    g_src[(size_t)NN * CAP];     // bucket CSR (row base = node*CAP)
__device__ float  g_dis[NN];
__device__ __half g_xh[EE];                    // fp16 dis[s]*x[s]  (NN*IND == EE)
__device__ __half g_w2h[WW * HD];              // fp16 fused [Wc2;Wv2]
__device__ __half g_h[(size_t)NN * WW];        // dis[n]*relu(layer1), fp16
__device__ __half g_aggh[(size_t)(NN + 32) * WW]; // A_norm @ h, fp16 (+pad rows)

// ---------------- graph build: ONE pass (atomic slot + scatter) ----------------
__global__ void k_build(const int* __restrict__ ei,
                        const float* __restrict__ Wc2,
                        const float* __restrict__ Wv2) {
    int e = blockIdx.x * blockDim.x + threadIdx.x;
    if (e < EE) {
        int d = ei[EE + e];
        int r = atomicAdd(&g_cnt[d], 1);
        g_src[(size_t)d * CAP + r] = ei[e];
    }
    if (e < WW * HD)
        g_w2h[e] = __float2half((e < HD * HD) ? Wc2[e] : Wv2[e - HD * HD]);
}

// self-loop + degree + dis; also writes xh = half(dis * x) row-wise
__global__ void k_dis(const float* __restrict__ x) {
    int i = blockIdx.x * blockDim.x + threadIdx.x;
    if (i < NN) {
        int c = g_cnt[i];
        g_src[(size_t)i * CAP + c] = i;        // self-loop in last slot
        g_deg[i] = c + 1;
        float di = rsqrtf((float)(c + 1));
        g_dis[i] = di;
        const float* xr = x + i * IND;
        __half2 o[8];
#pragma unroll
        for (int k = 0; k < 8; k++)
            o[k] = __floats2half2_rn(di * xr[k * 2], di * xr[k * 2 + 1]);
        *(uint4*)(g_xh + i * IND)     = *(uint4*)&o[0];
        *(uint4*)(g_xh + i * IND + 8) = *(uint4*)&o[4];
    }
}

// ---------------- shared fp16 sum helper (pure add, no weight) ----------------
__device__ __forceinline__ void sum8(float* acc, uint4 v) {
    float2 p;
    p = __half22float2(*(const __half2*)&v.x);
    acc[0] += p.x; acc[1] += p.y;
    p = __half22float2(*(((const __half2*)&v.x) + 1));
    acc[2] += p.x; acc[3] += p.y;
    p = __half22float2(*(const __half2*)&v.z);
    acc[4] += p.x; acc[5] += p.y;
    p = __half22float2(*(((const __half2*)&v.z) + 1));
    acc[6] += p.x; acc[7] += p.y;
}

// ------- fused layer 1: 16 nodes/block -------
__global__ void __launch_bounds__(256) k_layer1(const float* __restrict__ Wc1,
                                                const float* __restrict__ Wv1,
                                                const float* __restrict__ bc1,
                                                const float* __restrict__ bv1) {
    __shared__ float xs[16][IND];
    int t = threadIdx.x, w = t >> 5, lane = t & 31;
    int node0 = blockIdx.x * 16;

    // counter cleanup for next call
    int gid = blockIdx.x * 256 + t;
    if (gid < NN) g_cnt[gid] = 0;

    int slot = lane >> 1, part = lane & 1;     // 16 edge slots x 2 half-rows
#pragma unroll
    for (int q = 0; q < 2; q++) {
        int node = node0 + w * 2 + q;
        if (node < NN) {
            int jb = node * CAP, je = jb + g_deg[node];
            float acc[8];
#pragma unroll
            for (int i = 0; i < 8; i++) acc[i] = 0.f;
            for (int j = jb + slot; j < je; j += 16) {
                int s = g_src[j];
                uint4 xv = __ldg((const uint4*)(g_xh + s * IND) + part);
                sum8(acc, xv);
            }
#pragma unroll
            for (int off = 16; off >= 2; off >>= 1) {
#pragma unroll
                for (int i = 0; i < 8; i++)
                    acc[i] += __shfl_down_sync(0xffffffffu, acc[i], off);
            }
            if (lane < 2) {                    // apply dis[node] once here
                float di = g_dis[node];
                *(float4*)&xs[w * 2 + q][lane * 8] =
                    make_float4(di * acc[0], di * acc[1], di * acc[2], di * acc[3]);
                *(float4*)&xs[w * 2 + q][lane * 8 + 4] =
                    make_float4(di * acc[4], di * acc[5], di * acc[6], di * acc[7]);
            }
        }
    }
    __syncthreads();

    const float4* wr = (const float4*)((t < HD) ? (Wc1 + t * IND)
                                                : (Wv1 + (t - HD) * IND));
    float4 w0 = __ldg(&wr[0]), w1 = __ldg(&wr[1]);
    float4 w2 = __ldg(&wr[2]), w3 = __ldg(&wr[3]);
    float bias = (t < HD) ? __ldg(&bc1[t]) : __ldg(&bv1[t - HD]);
#pragma unroll
    for (int n = 0; n < 16; n++) {
        int node = node0 + n;
        if (node >= NN) break;
        float a = bias;
        a = fmaf(w0.x, xs[n][0],  a); a = fmaf(w0.y, xs[n][1],  a);
        a = fmaf(w0.z, xs[n][2],  a); a = fmaf(w0.w, xs[n][3],  a);
        a = fmaf(w1.x, xs[n][4],  a); a = fmaf(w1.y, xs[n][5],  a);
        a = fmaf(w1.z, xs[n][6],  a); a = fmaf(w1.w, xs[n][7],  a);
        a = fmaf(w2.x, xs[n][8],  a); a = fmaf(w2.y, xs[n][9],  a);
        a = fmaf(w2.z, xs[n][10], a); a = fmaf(w2.w, xs[n][11], a);
        a = fmaf(w3.x, xs[n][12], a); a = fmaf(w3.y, xs[n][13], a);
        a = fmaf(w3.z, xs[n][14], a); a = fmaf(w3.w, xs[n][15], a);
        g_h[(size_t)node * WW + t] = __float2half(g_dis[node] * fmaxf(a, 0.f));
    }
}

// ---------------- SpMM on h (256-wide, fp16 tree-sum gather) ----------------
__global__ void __launch_bounds__(256, 6) k_spmmh() {
    int w = threadIdx.x >> 5, lane = threadIdx.x & 31;
    int node = blockIdx.x * 8 + w;
    if (node >= NN) return;
    int jb = node * CAP;                       // 384B-aligned row base
    int deg = g_deg[node];
    const __half* hp = g_h + (size_t)lane * 8;
    float acc[8];
#pragma unroll
    for (int i = 0; i < 8; i++) acc[i] = 0.f;
    int j = 0;
    for (; j + 4 <= deg; j += 4) {
        int4 s4 = *(const int4*)&g_src[jb + j];   // one aligned LDG.128
        uint4 v0 = __ldg((const uint4*)(hp + (size_t)s4.x * WW));
        uint4 v1 = __ldg((const uint4*)(hp + (size_t)s4.y * WW));
        uint4 v2 = __ldg((const uint4*)(hp + (size_t)s4.z * WW));
        uint4 v3 = __ldg((const uint4*)(hp + (size_t)s4.w * WW));
        // fp16 tree-sum of the 4 vectors, one convert per 4 edges
        const __half2* p0 = (const __half2*)&v0;
        const __half2* p1 = (const __half2*)&v1;
        const __half2* p2 = (const __half2*)&v2;
        const __half2* p3 = (const __half2*)&v3;
#pragma unroll
        for (int i = 0; i < 4; i++) {
            __half2 s = __hadd2(__hadd2(p0[i], p1[i]), __hadd2(p2[i], p3[i]));
            float2 f = __half22float2(s);
            acc[i * 2]     += f.x;
            acc[i * 2 + 1] += f.y;
        }
    }
    for (; j < deg; j++) {
        int s = g_src[jb + j];
        uint4 v = __ldg((const uint4*)(hp + (size_t)s * WW));
        sum8(acc, v);
    }
    float di = g_dis[node];
    __half2 ho[4];
#pragma unroll
    for (int i = 0; i < 4; i++)
        ho[i] = __floats2half2_rn(di * acc[i * 2], di * acc[i * 2 + 1]);
    *(uint4*)(g_aggh + (size_t)node * WW + lane * 8) = *(uint4*)ho;
}

// ---------------- dense layer 2 + heads (tensor cores) ----------------
__global__ void __launch_bounds__(256)
k_gemm2t(const float* __restrict__ bc2, const float* __restrict__ bv2,
         const float* __restrict__ Wp,  const float* __restrict__ Wvh,
         const float* __restrict__ bp,  const float* __restrict__ bvh,
         float* __restrict__ out) {
    __shared__ __align__(16) char sbuf[32 * ZLD * 4];   // 33.8 KB
    __half* As = (__half*)sbuf;                         // [32][ZLD] halves
    float*  zs = (float*)sbuf;                          // [32][ZLD] floats
    int t = threadIdx.x, warp = t >> 5;
    int node0 = blockIdx.x * 32;

    {
        const uint4* src = (const uint4*)(g_aggh + (size_t)node0 * WW);
        uint4* dst = (uint4*)As;
#pragma unroll
        for (int i = 0; i < 4; i++) {
            int idx = t + i * 256;
            int m = idx >> 5, c8 = idx & 31;
            dst[m * (ZLD / 8) + c8] = src[m * (WW / 8) + c8];
        }
    }
    __syncthreads();

    int nb = warp * 32;
    int kb = (warp < 4) ? 0 : HD;
    const __half* Bbase = g_w2h + nb * HD;

    wmma::fragment<wmma::accumulator, 16, 16, 16, float> c[2][2];
#pragma unroll
    for (int mi = 0; mi < 2; mi++)
#pragma unroll
        for (int ni = 0; ni < 2; ni++) wmma::fill_fragment(c[mi][ni], 0.f);

#pragma unroll
    for (int k = 0; k < HD; k += 16) {
        wmma::fragment<wmma::matrix_a, 16, 16, 16, __half, wmma::row_major> a0, a1;
        wmma::load_matrix_sync(a0, As + kb + k, ZLD);
        wmma::load_matrix_sync(a1, As + 16 * ZLD + kb + k, ZLD);
        wmma::fragment<wmma::matrix_b, 16, 16, 16, __half, wmma::col_major> b0, b1;
        wmma::load_matrix_sync(b0, Bbase + k, HD);
        wmma::load_matrix_sync(b1, Bbase + 16 * HD + k, HD);
        wmma::mma_sync(c[0][0], a0, b0, c[0][0]);
        wmma::mma_sync(c[0][1], a0, b1, c[0][1]);
        wmma::mma_sync(c[1][0], a1, b0, c[1][0]);
        wmma::mma_sync(c[1][1], a1, b1, c[1][1]);
    }
    __syncthreads();

#pragma unroll
    for (int mi = 0; mi < 2; mi++)
#pragma unroll
        for (int ni = 0; ni < 2; ni++)
            wmma::store_matrix_sync(zs + (mi * 16) * ZLD + nb + ni * 16,
                                    c[mi][ni], ZLD, wmma::mem_row_major);
    __syncthreads();

    float bias = (t < HD) ? __ldg(&bc2[t]) : __ldg(&bv2[t - HD]);
    float hw   = (t < HD) ? __ldg(&Wp[t])  : __ldg(&Wvh[t - HD]);
#pragma unroll 8
    for (int n = 0; n < 32; n++) {
        float v = zs[n * ZLD + t];
        zs[n * ZLD + t] = fmaxf(v + bias, 0.f) * hw;
    }
    __syncthreads();

    int task = t >> 2, l4 = t & 3;
    int n = task & 31, half = task >> 5;
    const float* row = zs + n * ZLD + half * HD + l4 * 32;
    float s = 0.f;
#pragma unroll
    for (int i = 0; i < 32; i++) s += row[i];
    s += __shfl_down_sync(0xffffffffu, s, 1);
    s += __shfl_down_sync(0xffffffffu, s, 2);
    int node = node0 + n;
    if (l4 == 0 && node < NN) {
        if (half == 0) out[node]      = s + __ldg(&bp[0]);
        else           out[NN + node] = s + __ldg(&bvh[0]);
    }
}

// ---------------- launch (kernel launches ONLY) ----------------
extern "C" void kernel_launch(void* const* d_in, const int* in_sizes, int n_in,
                              void* d_out, int out_size) {
    const float* x   = (const float*)d_in[0];
    const int*   ei  = (const int*)d_in[1];
    const float* Wc1 = (const float*)d_in[2];
    const float* bc1 = (const float*)d_in[3];
    const float* Wc2 = (const float*)d_in[4];
    const float* bc2 = (const float*)d_in[5];
    const float* Wp  = (const float*)d_in[6];
    const float* bp  = (const float*)d_in[7];
    const float* Wv1 = (const float*)d_in[8];
    const float* bv1 = (const float*)d_in[9];
    const float* Wv2 = (const float*)d_in[10];
    const float* bv2 = (const float*)d_in[11];
    const float* Wvh = (const float*)d_in[12];
    const float* bvh = (const float*)d_in[13];
    float* out = (float*)d_out;

    k_build <<<(EE + 255) / 256, 256>>>(ei, Wc2, Wv2);
    k_dis   <<<(NN + 255) / 256, 256>>>(x);
    k_layer1<<<(NN + 15) / 16, 256>>>(Wc1, Wv1, bc1, bv1);
    k_spmmh <<<(NN + 7) / 8, 256>>>();
    k_gemm2t<<<(NN + 31) / 32, 256>>>(bc2, bv2, Wp, Wvh, bp, bvh, out);
}

// round 17
// speedup vs baseline: 1.2920x; 1.0296x over previous
#include <cuda_runtime.h>
#include <cuda_fp16.h>
#include <mma.h>
#include <cstdint>

using namespace nvcuda;

#define NN 50000
#define EE 800000
#define IND 16
#define HD 128
#define WW 256          // fused width (policy 0..127, value 128..255)
#define CAP 96          // bucket capacity per node (deg ~ Poisson(16))
#define ZLD 264         // z/A tile leading dim (elements)

// ---------------- device scratch (static, no allocation; zero-initialized) ----
__device__ int    g_cnt[NN];                   // zero on entry; re-zeroed by k_layer1
__device__ int    g_deg[NN];
__device__ int    g_src[(size_t)NN * CAP];     // bucket CSR (row base = node*CAP)
__device__ float  g_dis[NN];
__device__ __half g_xh[EE];                    // fp16 dis[s]*x[s]  (NN*IND == EE)
__device__ __half g_w2h[WW * HD];              // fp16 fused [Wc2;Wv2]
__device__ __half g_h[(size_t)NN * WW];        // dis[n]*relu(layer1), fp16

// ---------------- graph build: ONE pass (atomic slot + scatter) ----------------
__global__ void k_build(const int* __restrict__ ei,
                        const float* __restrict__ Wc2,
                        const float* __restrict__ Wv2) {
    int e = blockIdx.x * blockDim.x + threadIdx.x;
    if (e < EE) {
        int d = ei[EE + e];
        int r = atomicAdd(&g_cnt[d], 1);
        g_src[(size_t)d * CAP + r] = ei[e];
    }
    if (e < WW * HD)
        g_w2h[e] = __float2half((e < HD * HD) ? Wc2[e] : Wv2[e - HD * HD]);
}

// self-loop + degree + dis; also writes xh = half(dis * x) row-wise
__global__ void k_dis(const float* __restrict__ x) {
    int i = blockIdx.x * blockDim.x + threadIdx.x;
    if (i < NN) {
        int c = g_cnt[i];
        g_src[(size_t)i * CAP + c] = i;        // self-loop in last slot
        g_deg[i] = c + 1;
        float di = rsqrtf((float)(c + 1));
        g_dis[i] = di;
        const float* xr = x + i * IND;
        __half2 o[8];
#pragma unroll
        for (int k = 0; k < 8; k++)
            o[k] = __floats2half2_rn(di * xr[k * 2], di * xr[k * 2 + 1]);
        *(uint4*)(g_xh + i * IND)     = *(uint4*)&o[0];
        *(uint4*)(g_xh + i * IND + 8) = *(uint4*)&o[4];
    }
}

// ---------------- shared fp16 sum helper (pure add, no weight) ----------------
__device__ __forceinline__ void sum8(float* acc, uint4 v) {
    float2 p;
    p = __half22float2(*(const __half2*)&v.x);
    acc[0] += p.x; acc[1] += p.y;
    p = __half22float2(*(((const __half2*)&v.x) + 1));
    acc[2] += p.x; acc[3] += p.y;
    p = __half22float2(*(const __half2*)&v.z);
    acc[4] += p.x; acc[5] += p.y;
    p = __half22float2(*(((const __half2*)&v.z) + 1));
    acc[6] += p.x; acc[7] += p.y;
}

// ------- fused layer 1: 16 nodes/block -------
__global__ void __launch_bounds__(256) k_layer1(const float* __restrict__ Wc1,
                                                const float* __restrict__ Wv1,
                                                const float* __restrict__ bc1,
                                                const float* __restrict__ bv1) {
    __shared__ float xs[16][IND];
    int t = threadIdx.x, w = t >> 5, lane = t & 31;
    int node0 = blockIdx.x * 16;

    // counter cleanup for next call
    int gid = blockIdx.x * 256 + t;
    if (gid < NN) g_cnt[gid] = 0;

    int slot = lane >> 1, part = lane & 1;     // 16 edge slots x 2 half-rows
#pragma unroll
    for (int q = 0; q < 2; q++) {
        int node = node0 + w * 2 + q;
        if (node < NN) {
            int jb = node * CAP, je = jb + g_deg[node];
            float acc[8];
#pragma unroll
            for (int i = 0; i < 8; i++) acc[i] = 0.f;
            for (int j = jb + slot; j < je; j += 16) {
                int s = g_src[j];
                uint4 xv = __ldg((const uint4*)(g_xh + s * IND) + part);
                sum8(acc, xv);
            }
#pragma unroll
            for (int off = 16; off >= 2; off >>= 1) {
#pragma unroll
                for (int i = 0; i < 8; i++)
                    acc[i] += __shfl_down_sync(0xffffffffu, acc[i], off);
            }
            if (lane < 2) {                    // apply dis[node] once here
                float di = g_dis[node];
                *(float4*)&xs[w * 2 + q][lane * 8] =
                    make_float4(di * acc[0], di * acc[1], di * acc[2], di * acc[3]);
                *(float4*)&xs[w * 2 + q][lane * 8 + 4] =
                    make_float4(di * acc[4], di * acc[5], di * acc[6], di * acc[7]);
            }
        }
    }
    __syncthreads();

    const float4* wr = (const float4*)((t < HD) ? (Wc1 + t * IND)
                                                : (Wv1 + (t - HD) * IND));
    float4 w0 = __ldg(&wr[0]), w1 = __ldg(&wr[1]);
    float4 w2 = __ldg(&wr[2]), w3 = __ldg(&wr[3]);
    float bias = (t < HD) ? __ldg(&bc1[t]) : __ldg(&bv1[t - HD]);
#pragma unroll
    for (int n = 0; n < 16; n++) {
        int node = node0 + n;
        if (node >= NN) break;
        float a = bias;
        a = fmaf(w0.x, xs[n][0],  a); a = fmaf(w0.y, xs[n][1],  a);
        a = fmaf(w0.z, xs[n][2],  a); a = fmaf(w0.w, xs[n][3],  a);
        a = fmaf(w1.x, xs[n][4],  a); a = fmaf(w1.y, xs[n][5],  a);
        a = fmaf(w1.z, xs[n][6],  a); a = fmaf(w1.w, xs[n][7],  a);
        a = fmaf(w2.x, xs[n][8],  a); a = fmaf(w2.y, xs[n][9],  a);
        a = fmaf(w2.z, xs[n][10], a); a = fmaf(w2.w, xs[n][11], a);
        a = fmaf(w3.x, xs[n][12], a); a = fmaf(w3.y, xs[n][13], a);
        a = fmaf(w3.z, xs[n][14], a); a = fmaf(w3.w, xs[n][15], a);
        g_h[(size_t)node * WW + t] = __float2half(g_dis[node] * fmaxf(a, 0.f));
    }
}

// ---------- fused SpMM + dense layer 2 + heads (gather -> smem -> wmma) -------
// 32 nodes/block. Gather phase: 8 warps x 4 nodes, lane owns 8 cols, fp16
// tree-sum (same loop as the standalone spmmh). Results land directly in the
// smem A-tile. MMA phase: warp owns a 32-col slab; epilogue reduces heads.
__global__ void __launch_bounds__(256)
k_spmm2t(const float* __restrict__ bc2, const float* __restrict__ bv2,
         const float* __restrict__ Wp,  const float* __restrict__ Wvh,
         const float* __restrict__ bp,  const float* __restrict__ bvh,
         float* __restrict__ out) {
    __shared__ __align__(16) char sbuf[32 * ZLD * 4];   // 33.8 KB
    __half* As = (__half*)sbuf;                         // [32][ZLD] halves
    float*  zs = (float*)sbuf;                          // [32][ZLD] floats
    int t = threadIdx.x, warp = t >> 5, lane = t & 31;
    int node0 = blockIdx.x * 32;

    // ---- gather phase: aggregate 4 nodes per warp into As ----
#pragma unroll
    for (int q = 0; q < 4; q++) {
        int m = warp * 4 + q;
        int node = node0 + m;
        uint4 ho = {0u, 0u, 0u, 0u};
        if (node < NN) {
            int jb = node * CAP;
            int deg = g_deg[node];
            const __half* hp = g_h + (size_t)lane * 8;
            float acc[8];
#pragma unroll
            for (int i = 0; i < 8; i++) acc[i] = 0.f;
            int j = 0;
            for (; j + 4 <= deg; j += 4) {
                int4 s4 = *(const int4*)&g_src[jb + j];
                uint4 v0 = __ldg((const uint4*)(hp + (size_t)s4.x * WW));
                uint4 v1 = __ldg((const uint4*)(hp + (size_t)s4.y * WW));
                uint4 v2 = __ldg((const uint4*)(hp + (size_t)s4.z * WW));
                uint4 v3 = __ldg((const uint4*)(hp + (size_t)s4.w * WW));
                const __half2* p0 = (const __half2*)&v0;
                const __half2* p1 = (const __half2*)&v1;
                const __half2* p2 = (const __half2*)&v2;
                const __half2* p3 = (const __half2*)&v3;
#pragma unroll
                for (int i = 0; i < 4; i++) {
                    __half2 s = __hadd2(__hadd2(p0[i], p1[i]), __hadd2(p2[i], p3[i]));
                    float2 f = __half22float2(s);
                    acc[i * 2]     += f.x;
                    acc[i * 2 + 1] += f.y;
                }
            }
            for (; j < deg; j++) {
                int s = g_src[jb + j];
                uint4 v = __ldg((const uint4*)(hp + (size_t)s * WW));
                sum8(acc, v);
            }
            float di = g_dis[node];
            __half2* hop = (__half2*)&ho;
#pragma unroll
            for (int i = 0; i < 4; i++)
                hop[i] = __floats2half2_rn(di * acc[i * 2], di * acc[i * 2 + 1]);
        }
        *(uint4*)(As + m * ZLD + lane * 8) = ho;
    }
    __syncthreads();

    // ---- MMA phase ----
    int nb = warp * 32;
    int kb = (warp < 4) ? 0 : HD;
    const __half* Bbase = g_w2h + nb * HD;

    wmma::fragment<wmma::accumulator, 16, 16, 16, float> c[2][2];
#pragma unroll
    for (int mi = 0; mi < 2; mi++)
#pragma unroll
        for (int ni = 0; ni < 2; ni++) wmma::fill_fragment(c[mi][ni], 0.f);

#pragma unroll
    for (int k = 0; k < HD; k += 16) {
        wmma::fragment<wmma::matrix_a, 16, 16, 16, __half, wmma::row_major> a0, a1;
        wmma::load_matrix_sync(a0, As + kb + k, ZLD);
        wmma::load_matrix_sync(a1, As + 16 * ZLD + kb + k, ZLD);
        wmma::fragment<wmma::matrix_b, 16, 16, 16, __half, wmma::col_major> b0, b1;
        wmma::load_matrix_sync(b0, Bbase + k, HD);
        wmma::load_matrix_sync(b1, Bbase + 16 * HD + k, HD);
        wmma::mma_sync(c[0][0], a0, b0, c[0][0]);
        wmma::mma_sync(c[0][1], a0, b1, c[0][1]);
        wmma::mma_sync(c[1][0], a1, b0, c[1][0]);
        wmma::mma_sync(c[1][1], a1, b1, c[1][1]);
    }
    __syncthreads();   // done reading As; reuse as zs

#pragma unroll
    for (int mi = 0; mi < 2; mi++)
#pragma unroll
        for (int ni = 0; ni < 2; ni++)
            wmma::store_matrix_sync(zs + (mi * 16) * ZLD + nb + ni * 16,
                                    c[mi][ni], ZLD, wmma::mem_row_major);
    __syncthreads();

    float bias = (t < HD) ? __ldg(&bc2[t]) : __ldg(&bv2[t - HD]);
    float hw   = (t < HD) ? __ldg(&Wp[t])  : __ldg(&Wvh[t - HD]);
#pragma unroll 8
    for (int n = 0; n < 32; n++) {
        float v = zs[n * ZLD + t];
        zs[n * ZLD + t] = fmaxf(v + bias, 0.f) * hw;
    }
    __syncthreads();

    int task = t >> 2, l4 = t & 3;
    int n = task & 31, half = task >> 5;
    const float* row = zs + n * ZLD + half * HD + l4 * 32;
    float s = 0.f;
#pragma unroll
    for (int i = 0; i < 32; i++) s += row[i];
    s += __shfl_down_sync(0xffffffffu, s, 1);
    s += __shfl_down_sync(0xffffffffu, s, 2);
    int node = node0 + n;
    if (l4 == 0 && node < NN) {
        if (half == 0) out[node]      = s + __ldg(&bp[0]);
        else           out[NN + node] = s + __ldg(&bvh[0]);
    }
}

// ---------------- launch (kernel launches ONLY) ----------------
extern "C" void kernel_launch(void* const* d_in, const int* in_sizes, int n_in,
                              void* d_out, int out_size) {
    const float* x   = (const float*)d_in[0];
    const int*   ei  = (const int*)d_in[1];
    const float* Wc1 = (const float*)d_in[2];
    const float* bc1 = (const float*)d_in[3];
    const float* Wc2 = (const float*)d_in[4];
    const float* bc2 = (const float*)d_in[5];
    const float* Wp  = (const float*)d_in[6];
    const float* bp  = (const float*)d_in[7];
    const float* Wv1 = (const float*)d_in[8];
    const float* bv1 = (const float*)d_in[9];
    const float* Wv2 = (const float*)d_in[10];
    const float* bv2 = (const float*)d_in[11];
    const float* Wvh = (const float*)d_in[12];
    const float* bvh = (const float*)d_in[13];
    float* out = (float*)d_out;

    k_build <<<(EE + 255) / 256, 256>>>(ei, Wc2, Wv2);
    k_dis   <<<(NN + 255) / 256, 256>>>(x);
    k_layer1<<<(NN + 15) / 16, 256>>>(Wc1, Wv1, bc1, bv1);
    k_spmm2t<<<(NN + 31) / 32, 256>>>(bc2, bv2, Wp, Wvh, bp, bvh, out);
}